// round 3
// baseline (speedup 1.0000x reference)
#include <cuda_runtime.h>
#include <cuda_bf16.h>

// Problem constants
#define NN     20000
#define IN_DIM 256
#define NH     3
#define ND     64
#define HD     192          // NH*ND
#define EE     640000
#define NHD    (NN*HD)      // 3,840,000
#define NEG_SLOPE 0.2f

// ---------------- scratch (device globals; no allocation) ----------------
__device__ __align__(16) float g_h[NN * HD];       // projected features [N,H,D]
__device__ float g_el[NN * NH];
__device__ float g_er[NN * NH];
__device__ float g_m[NN * NH];                     // segment max
__device__ float g_denom[NN * NH];                 // segment sum of exp
__device__ __align__(16) float g_e[EE * NH];       // e -> ex -> alpha (in place)
__device__ __align__(16) float g_out[NN * HD];     // aggregated output [N,H,D]
__device__ int   g_is64;                           // 1 if src/dst are int64

// ---------------- helpers ----------------
__device__ __forceinline__ int get_idx(const void* p, int i) {
    if (g_is64) return (int)((const long long*)p)[i];
    return ((const int*)p)[i];
}

__device__ __forceinline__ void atomicMaxF(float* addr, float v) {
    if (v >= 0.0f) atomicMax((int*)addr, __float_as_int(v));
    else           atomicMin((unsigned int*)addr, __float_as_uint(v));
}

// ---------------- dtype detection for src/dst ----------------
// If data is int64 (values in [0, 2^31)), every odd 32-bit word is 0.
// If data is int32 (random in [0,20000)), odd words are the next values
// (nonzero with overwhelming probability over 1024 samples).
__global__ void k_detect(const void* src, const void* dst) {
    __shared__ int found;
    if (threadIdx.x == 0) found = 0;
    __syncthreads();
    const int* s32 = (const int*)src;
    const int* d32 = (const int*)dst;
    for (int k = threadIdx.x; k < 1024; k += blockDim.x) {
        if (s32[2 * k + 1] != 0 || d32[2 * k + 1] != 0) found = 1;
    }
    __syncthreads();
    if (threadIdx.x == 0) g_is64 = found ? 0 : 1;
}

// ---------------- init: zero out, -inf max, zero denom, d_out = fc_b ----------------
__global__ void k_init(const float* __restrict__ fc_b, float* __restrict__ out2) {
    int stride = gridDim.x * blockDim.x;
    for (int i = blockIdx.x * blockDim.x + threadIdx.x; i < NHD; i += stride) {
        g_out[i] = 0.0f;
        if (i < NN * NH) { g_m[i] = __int_as_float(0xff800000); g_denom[i] = 0.0f; }
        if (i < 2) out2[i] = fc_b[i];
    }
}

// ---------------- SGEMM: g_h = feat[20000,256] @ W[256,192] ----------------
// 64x64 tile per block, BK=16, 256 threads, 4x4 micro-tile.
__global__ __launch_bounds__(256) void k_gemm(const float* __restrict__ feat,
                                              const float* __restrict__ W) {
    __shared__ float As[16][64];   // A^T tile: [k][m]
    __shared__ float Bs[16][64];   // [k][n]

    const int m0 = blockIdx.x * 64;
    const int n0 = blockIdx.y * 64;
    const int tid = threadIdx.x;
    const int tx = tid & 15;       // n
    const int ty = tid >> 4;       // m

    float acc[4][4];
#pragma unroll
    for (int i = 0; i < 4; i++)
#pragma unroll
        for (int j = 0; j < 4; j++) acc[i][j] = 0.0f;

    const float4* feat4 = (const float4*)feat;
    const float4* W4 = (const float4*)W;

    // A-load mapping: m = tid>>2 (0..63), kg = tid&3 (k-group of 4)
    const int am = tid >> 2;
    const int akg = tid & 3;
    // B-load mapping: kk = tid>>4 (0..15), ng = tid&15 (n-group of 4)
    const int bkk = tid >> 4;
    const int bng = tid & 15;

    for (int k0 = 0; k0 < IN_DIM; k0 += 16) {
        // load A tile (transposed into smem)
        float4 av = make_float4(0.f, 0.f, 0.f, 0.f);
        if (m0 + am < NN)
            av = feat4[(size_t)(m0 + am) * (IN_DIM / 4) + (k0 >> 2) + akg];
        As[akg * 4 + 0][am] = av.x;
        As[akg * 4 + 1][am] = av.y;
        As[akg * 4 + 2][am] = av.z;
        As[akg * 4 + 3][am] = av.w;
        // load B tile
        float4 bv = W4[(size_t)(k0 + bkk) * (HD / 4) + (n0 >> 2) + bng];
        *(float4*)&Bs[bkk][bng * 4] = bv;
        __syncthreads();

#pragma unroll
        for (int kk = 0; kk < 16; kk++) {
            float4 a = *(const float4*)&As[kk][ty * 4];
            float4 b = *(const float4*)&Bs[kk][tx * 4];
            acc[0][0] += a.x * b.x; acc[0][1] += a.x * b.y; acc[0][2] += a.x * b.z; acc[0][3] += a.x * b.w;
            acc[1][0] += a.y * b.x; acc[1][1] += a.y * b.y; acc[1][2] += a.y * b.z; acc[1][3] += a.y * b.w;
            acc[2][0] += a.z * b.x; acc[2][1] += a.z * b.y; acc[2][2] += a.z * b.z; acc[2][3] += a.z * b.w;
            acc[3][0] += a.w * b.x; acc[3][1] += a.w * b.y; acc[3][2] += a.w * b.z; acc[3][3] += a.w * b.w;
        }
        __syncthreads();
    }

#pragma unroll
    for (int i = 0; i < 4; i++) {
        int m = m0 + ty * 4 + i;
        if (m < NN) {
            float4 v = make_float4(acc[i][0], acc[i][1], acc[i][2], acc[i][3]);
            *(float4*)&g_h[(size_t)m * HD + n0 + tx * 4] = v;
        }
    }
}

// ---------------- el / er: per-node per-head dot with attn vectors ----------------
// block = 96 threads = 3 warps; warp w handles head w of node blockIdx.x
__global__ __launch_bounds__(96) void k_attn(const float* __restrict__ al,
                                             const float* __restrict__ ar) {
    int n = blockIdx.x;
    int w = threadIdx.x >> 5;
    int lane = threadIdx.x & 31;
    const float* hrow = g_h + (size_t)n * HD + w * ND;
    float v0 = hrow[lane], v1 = hrow[lane + 32];
    float l = v0 * al[w * ND + lane] + v1 * al[w * ND + lane + 32];
    float r = v0 * ar[w * ND + lane] + v1 * ar[w * ND + lane + 32];
#pragma unroll
    for (int o = 16; o > 0; o >>= 1) {
        l += __shfl_down_sync(0xffffffffu, l, o);
        r += __shfl_down_sync(0xffffffffu, r, o);
    }
    if (lane == 0) { g_el[n * NH + w] = l; g_er[n * NH + w] = r; }
}

// ---------------- edge pass 1: logits + segment max ----------------
__global__ __launch_bounds__(256) void k_edge_logits(const void* src, const void* dst) {
    int e = blockIdx.x * blockDim.x + threadIdx.x;
    if (e >= EE) return;
    int s = get_idx(src, e);
    int d = get_idx(dst, e);
#pragma unroll
    for (int h = 0; h < NH; h++) {
        float x = g_el[s * NH + h] + g_er[d * NH + h];
        x = (x > 0.0f) ? x : NEG_SLOPE * x;
        g_e[(size_t)e * NH + h] = x;
        atomicMaxF(&g_m[d * NH + h], x);
    }
}

// ---------------- edge pass 2: exp + segment sum ----------------
__global__ __launch_bounds__(256) void k_edge_exp(const void* dst) {
    int e = blockIdx.x * blockDim.x + threadIdx.x;
    if (e >= EE) return;
    int d = get_idx(dst, e);
#pragma unroll
    for (int h = 0; h < NH; h++) {
        float ex = expf(g_e[(size_t)e * NH + h] - g_m[d * NH + h]);
        g_e[(size_t)e * NH + h] = ex;
        atomicAdd(&g_denom[d * NH + h], ex);
    }
}

// ---------------- edge pass 3: alpha = ex / denom[dst] ----------------
__global__ __launch_bounds__(256) void k_edge_alpha(const void* dst) {
    int i = blockIdx.x * blockDim.x + threadIdx.x;
    if (i >= EE * NH) return;
    int e = i / NH;
    int h = i - e * NH;
    int d = get_idx(dst, e);
    g_e[i] = g_e[i] / g_denom[d * NH + h];
}

// ---------------- aggregation: out[dst] += alpha * h[src] ----------------
// 48 threads per edge, one float4 each (192 floats). Vector RED to L2.
__global__ __launch_bounds__(256) void k_agg(const void* src, const void* dst) {
    int t = blockIdx.x * blockDim.x + threadIdx.x;   // < EE*48 = 30,720,000
    int e = t / 48;
    int j = t - e * 48;
    int s = get_idx(src, e);
    int d = get_idx(dst, e);
    float a = g_e[(size_t)e * NH + (j >> 4)];        // head = j/16
    float4 hv = *(const float4*)&g_h[(size_t)s * HD + j * 4];
    float x = hv.x * a, y = hv.y * a, z = hv.z * a, w = hv.w * a;
    float* p = &g_out[(size_t)d * HD + j * 4];
    asm volatile("red.global.add.v4.f32 [%0], {%1, %2, %3, %4};"
                 :: "l"(p), "f"(x), "f"(y), "f"(z), "f"(w) : "memory");
}

// ---------------- final: relu(out + bias) flattened, dot with fc_w ----------------
__global__ __launch_bounds__(256) void k_fc(const float* __restrict__ gat_bias,
                                            const float* __restrict__ fc_w,
                                            float* __restrict__ out2) {
    float a0 = 0.0f, a1 = 0.0f;
    int stride = gridDim.x * blockDim.x;
    const float2* w2 = (const float2*)fc_w;
    for (int i = blockIdx.x * blockDim.x + threadIdx.x; i < NHD; i += stride) {
        float v = g_out[i] + gat_bias[i % HD];
        v = fmaxf(v, 0.0f);
        float2 wv = w2[i];
        a0 += v * wv.x;
        a1 += v * wv.y;
    }
    __shared__ float s0[256], s1[256];
    int tid = threadIdx.x;
    s0[tid] = a0; s1[tid] = a1;
    __syncthreads();
    for (int o = 128; o > 0; o >>= 1) {
        if (tid < o) { s0[tid] += s0[tid + o]; s1[tid] += s1[tid + o]; }
        __syncthreads();
    }
    if (tid == 0) {
        atomicAdd(&out2[0], s0[0]);
        atomicAdd(&out2[1], s1[0]);
    }
}

// ---------------- launch ----------------
extern "C" void kernel_launch(void* const* d_in, const int* in_sizes, int n_in,
                              void* d_out, int out_size) {
    const float* feat     = (const float*)d_in[0];
    const float* W        = (const float*)d_in[1];
    const float* attn_l   = (const float*)d_in[2];
    const float* attn_r   = (const float*)d_in[3];
    const float* gat_bias = (const float*)d_in[4];
    const float* fc_w     = (const float*)d_in[5];
    const float* fc_b     = (const float*)d_in[6];
    const void*  src      = d_in[7];
    const void*  dst      = d_in[8];
    float* out2 = (float*)d_out;

    k_detect<<<1, 256>>>(src, dst);
    k_init<<<2048, 256>>>(fc_b, out2);
    k_gemm<<<dim3((NN + 63) / 64, HD / 64), 256>>>(feat, W);
    k_attn<<<NN, 96>>>(attn_l, attn_r);
    k_edge_logits<<<(EE + 255) / 256, 256>>>(src, dst);
    k_edge_exp<<<(EE + 255) / 256, 256>>>(dst);
    k_edge_alpha<<<(EE * NH + 255) / 256, 256>>>(dst);
    k_agg<<<(EE * 48) / 256, 256>>>(src, dst);   // 120000 blocks, exact
    k_fc<<<2048, 256>>>(gat_bias, fc_w, out2);
}

// round 4
// speedup vs baseline: 1.4340x; 1.4340x over previous
#include <cuda_runtime.h>
#include <cuda_bf16.h>

// Problem constants
#define NN     20000
#define IN_DIM 256
#define NH     3
#define ND     64
#define HD     192          // NH*ND
#define EE     640000
#define NEG_SLOPE 0.2f

// ---------------- scratch (device globals; no allocation) ----------------
__device__ __align__(16) float g_h[NN * HD];       // projected features [N,H,D]
__device__ float g_el[NN * NH];
__device__ float g_er[NN * NH];
__device__ int   g_deg[NN];                        // in-degree histogram
__device__ int   g_ptr[NN + 1];                    // CSR row pointers (by dst)
__device__ int   g_cursor[NN];                     // scatter cursors
__device__ int   g_bsum[32];                       // scan block sums
__device__ __align__(16) int4 g_slots[EE];         // {src, t0, t1, t2} per edge, CSR order
__device__ float g_part[256];                      // 128 buckets x 2 FC partials
__device__ int   g_is64;

// ---------------- dtype detection for src/dst ----------------
__global__ void k_detect(const void* src, const void* dst) {
    __shared__ int found;
    if (threadIdx.x == 0) found = 0;
    __syncthreads();
    const int* s32 = (const int*)src;
    const int* d32 = (const int*)dst;
    for (int k = threadIdx.x; k < 1024; k += blockDim.x) {
        if (s32[2 * k + 1] != 0 || d32[2 * k + 1] != 0) found = 1;
    }
    __syncthreads();
    if (threadIdx.x == 0) g_is64 = found ? 0 : 1;
}

__device__ __forceinline__ int get_idx(const void* p, int i) {
    if (g_is64) return (int)((const long long*)p)[i];
    return ((const int*)p)[i];
}

// ---------------- init: zero histogram + FC partial buckets ----------------
__global__ void k_init() {
    int i = blockIdx.x * blockDim.x + threadIdx.x;
    if (i < NN) g_deg[i] = 0;
    if (i < 256) g_part[i] = 0.0f;
}

// ---------------- SGEMM + fused el/er epilogue ----------------
// h = feat[20000,256] @ W[256,192]; 64x64 tile, BK=16, 256 thr, 4x4 micro-tile.
// blockIdx.y == head (since ND == tile-N == 64): el/er computed exactly per block.
__global__ __launch_bounds__(256) void k_gemm(const float* __restrict__ feat,
                                              const float* __restrict__ W,
                                              const float* __restrict__ al,
                                              const float* __restrict__ ar) {
    __shared__ float As[16][64];   // A^T tile: [k][m]
    __shared__ float Bs[16][64];   // [k][n]
    __shared__ float rl[64][16];
    __shared__ float rr[64][16];

    const int m0 = blockIdx.x * 64;
    const int n0 = blockIdx.y * 64;
    const int head = blockIdx.y;
    const int tid = threadIdx.x;
    const int tx = tid & 15;       // n
    const int ty = tid >> 4;       // m

    float acc[4][4];
#pragma unroll
    for (int i = 0; i < 4; i++)
#pragma unroll
        for (int j = 0; j < 4; j++) acc[i][j] = 0.0f;

    const float4* feat4 = (const float4*)feat;
    const float4* W4 = (const float4*)W;

    const int am = tid >> 2;
    const int akg = tid & 3;
    const int bkk = tid >> 4;
    const int bng = tid & 15;

    for (int k0 = 0; k0 < IN_DIM; k0 += 16) {
        float4 av = make_float4(0.f, 0.f, 0.f, 0.f);
        if (m0 + am < NN)
            av = feat4[(size_t)(m0 + am) * (IN_DIM / 4) + (k0 >> 2) + akg];
        As[akg * 4 + 0][am] = av.x;
        As[akg * 4 + 1][am] = av.y;
        As[akg * 4 + 2][am] = av.z;
        As[akg * 4 + 3][am] = av.w;
        float4 bv = W4[(size_t)(k0 + bkk) * (HD / 4) + (n0 >> 2) + bng];
        *(float4*)&Bs[bkk][bng * 4] = bv;
        __syncthreads();

#pragma unroll
        for (int kk = 0; kk < 16; kk++) {
            float4 a = *(const float4*)&As[kk][ty * 4];
            float4 b = *(const float4*)&Bs[kk][tx * 4];
            acc[0][0] += a.x * b.x; acc[0][1] += a.x * b.y; acc[0][2] += a.x * b.z; acc[0][3] += a.x * b.w;
            acc[1][0] += a.y * b.x; acc[1][1] += a.y * b.y; acc[1][2] += a.y * b.z; acc[1][3] += a.y * b.w;
            acc[2][0] += a.z * b.x; acc[2][1] += a.z * b.y; acc[2][2] += a.z * b.z; acc[2][3] += a.z * b.w;
            acc[3][0] += a.w * b.x; acc[3][1] += a.w * b.y; acc[3][2] += a.w * b.z; acc[3][3] += a.w * b.w;
        }
        __syncthreads();
    }

    // store h tile
#pragma unroll
    for (int i = 0; i < 4; i++) {
        int m = m0 + ty * 4 + i;
        if (m < NN) {
            float4 v = make_float4(acc[i][0], acc[i][1], acc[i][2], acc[i][3]);
            *(float4*)&g_h[(size_t)m * HD + n0 + tx * 4] = v;
        }
    }

    // fused el/er epilogue: dot rows with attn vectors (cols of this block span the full head)
    float4 alv = *(const float4*)&al[head * ND + tx * 4];
    float4 arv = *(const float4*)&ar[head * ND + tx * 4];
#pragma unroll
    for (int i = 0; i < 4; i++) {
        float dl = acc[i][0] * alv.x + acc[i][1] * alv.y + acc[i][2] * alv.z + acc[i][3] * alv.w;
        float dr = acc[i][0] * arv.x + acc[i][1] * arv.y + acc[i][2] * arv.z + acc[i][3] * arv.w;
        rl[ty * 4 + i][tx] = dl;
        rr[ty * 4 + i][tx] = dr;
    }
    __syncthreads();
    if (tid < 64) {
        int m = m0 + tid;
        if (m < NN) {
            float sl = 0.f, sr = 0.f;
#pragma unroll
            for (int j = 0; j < 16; j++) { sl += rl[tid][j]; sr += rr[tid][j]; }
            g_el[m * NH + head] = sl;
            g_er[m * NH + head] = sr;
        }
    }
}

// ---------------- CSR build ----------------
__global__ __launch_bounds__(256) void k_hist(const void* dst) {
    int e = blockIdx.x * blockDim.x + threadIdx.x;
    if (e >= EE) return;
    atomicAdd(&g_deg[get_idx(dst, e)], 1);
}

// scan pass 1: per-block (chunk = 1000) sums. 20 blocks x 1024.
__global__ __launch_bounds__(1024) void k_scan1() {
    __shared__ int s[1024];
    int t = threadIdx.x;
    int i = blockIdx.x * 1000 + t;
    s[t] = (t < 1000) ? g_deg[i] : 0;
    __syncthreads();
    for (int o = 512; o > 0; o >>= 1) {
        if (t < o) s[t] += s[t + o];
        __syncthreads();
    }
    if (t == 0) g_bsum[blockIdx.x] = s[0];
}

// scan pass 2: block-local inclusive scan + global offset; writes ptr + cursor.
__global__ __launch_bounds__(1024) void k_scan2() {
    __shared__ int s[1024];
    __shared__ int offs;
    int t = threadIdx.x;
    int b = blockIdx.x;
    int i = b * 1000 + t;
    int d = (t < 1000) ? g_deg[i] : 0;
    s[t] = d;
    if (t == 0) {
        int o = 0;
        for (int j = 0; j < b; j++) o += g_bsum[j];
        offs = o;
    }
    __syncthreads();
    // Hillis-Steele inclusive scan
    for (int o = 1; o < 1024; o <<= 1) {
        int v = (t >= o) ? s[t - o] : 0;
        __syncthreads();
        s[t] += v;
        __syncthreads();
    }
    if (t < 1000) {
        int incl = offs + s[t];
        g_ptr[i + 1] = incl;
        g_cursor[i] = incl - d;
        if (i == 0) g_ptr[0] = 0;
    }
}

// scatter edges into CSR order; precompute t_h = exp(leakyrelu(el[src]+er[dst]))
__global__ __launch_bounds__(256) void k_scatter(const void* src, const void* dst) {
    int e = blockIdx.x * blockDim.x + threadIdx.x;
    if (e >= EE) return;
    int s = get_idx(src, e);
    int d = get_idx(dst, e);
    int pos = atomicAdd(&g_cursor[d], 1);
    int4 slot;
    slot.x = s;
    float tv[NH];
#pragma unroll
    for (int h = 0; h < NH; h++) {
        float x = g_el[s * NH + h] + g_er[d * NH + h];
        x = (x > 0.0f) ? x : NEG_SLOPE * x;
        tv[h] = expf(x);   // max-subtraction unnecessary: logits bounded small; alpha invariant
    }
    slot.y = __float_as_int(tv[0]);
    slot.z = __float_as_int(tv[1]);
    slot.w = __float_as_int(tv[2]);
    g_slots[pos] = slot;
}

// ---------------- fused per-node softmax-aggregate + bias + relu + FC ----------------
// one block (96 thr = 3 warps) per node; warp = head; lane owns float2 of D.
__global__ __launch_bounds__(96) void k_node(const float* __restrict__ gat_bias,
                                             const float* __restrict__ fc_w) {
    const int v = blockIdx.x;
    const int head = threadIdx.x >> 5;
    const int lane = threadIdx.x & 31;

    const int p0 = g_ptr[v];
    const int p1 = g_ptr[v + 1];

    float ax = 0.f, ay = 0.f, denom = 0.f;
    const float* hbase = g_h + (size_t)head * ND + lane * 2;

    for (int k = p0; k < p1; k++) {
        int4 slot = g_slots[k];                       // uniform across warp -> broadcast
        float t = __int_as_float(head == 0 ? slot.y : (head == 1 ? slot.z : slot.w));
        float2 hv = *(const float2*)(hbase + (size_t)slot.x * HD);
        ax += t * hv.x;
        ay += t * hv.y;
        denom += t;
    }

    float inv = (denom > 0.f) ? (1.0f / denom) : 0.0f;
    float2 bv = *(const float2*)&gat_bias[head * ND + lane * 2];
    float o0 = fmaxf(ax * inv + bv.x, 0.0f);
    float o1 = fmaxf(ay * inv + bv.y, 0.0f);

    // FC rows r0 = v*HD + head*ND + lane*2, r1 = r0+1 ; fc_w is [NHD][2]
    size_t r0 = (size_t)v * HD + head * ND + lane * 2;
    float4 w = *(const float4*)&fc_w[r0 * 2];
    float a0 = o0 * w.x + o1 * w.z;
    float a1 = o0 * w.y + o1 * w.w;

#pragma unroll
    for (int o = 16; o > 0; o >>= 1) {
        a0 += __shfl_down_sync(0xffffffffu, a0, o);
        a1 += __shfl_down_sync(0xffffffffu, a1, o);
    }
    __shared__ float sm[3][2];
    if (lane == 0) { sm[head][0] = a0; sm[head][1] = a1; }
    __syncthreads();
    if (threadIdx.x == 0) {
        float t0 = sm[0][0] + sm[1][0] + sm[2][0];
        float t1 = sm[0][1] + sm[1][1] + sm[2][1];
        int bucket = (v & 127) * 2;
        atomicAdd(&g_part[bucket], t0);
        atomicAdd(&g_part[bucket + 1], t1);
    }
}

// ---------------- final reduce ----------------
__global__ __launch_bounds__(128) void k_final(const float* __restrict__ fc_b,
                                               float* __restrict__ out2) {
    __shared__ float s0[128], s1[128];
    int t = threadIdx.x;
    s0[t] = g_part[t * 2];
    s1[t] = g_part[t * 2 + 1];
    __syncthreads();
    for (int o = 64; o > 0; o >>= 1) {
        if (t < o) { s0[t] += s0[t + o]; s1[t] += s1[t + o]; }
        __syncthreads();
    }
    if (t == 0) {
        out2[0] = s0[0] + fc_b[0];
        out2[1] = s1[0] + fc_b[1];
    }
}

// ---------------- launch ----------------
extern "C" void kernel_launch(void* const* d_in, const int* in_sizes, int n_in,
                              void* d_out, int out_size) {
    const float* feat     = (const float*)d_in[0];
    const float* W        = (const float*)d_in[1];
    const float* attn_l   = (const float*)d_in[2];
    const float* attn_r   = (const float*)d_in[3];
    const float* gat_bias = (const float*)d_in[4];
    const float* fc_w     = (const float*)d_in[5];
    const float* fc_b     = (const float*)d_in[6];
    const void*  src      = d_in[7];
    const void*  dst      = d_in[8];
    float* out2 = (float*)d_out;

    k_detect<<<1, 256>>>(src, dst);
    k_init<<<(NN + 511) / 512, 512>>>();
    k_gemm<<<dim3((NN + 63) / 64, NH), 256>>>(feat, W, attn_l, attn_r);
    k_hist<<<(EE + 255) / 256, 256>>>(dst);
    k_scan1<<<20, 1024>>>();
    k_scan2<<<20, 1024>>>();
    k_scatter<<<(EE + 255) / 256, 256>>>(src, dst);
    k_node<<<NN, 96>>>(gat_bias, fc_w);
    k_final<<<1, 128>>>(fc_b, out2);
}